// round 5
// baseline (speedup 1.0000x reference)
#include <cuda_runtime.h>
#include <math.h>

#define NN 50000
#define NE 800000
#define GD 128
#define LG 16

// ---- scratch (device globals: no allocations allowed) ----
__device__ float g_ns [NN * LG];        // silu(node_s @ Wns + bns)
__device__ float g_nv [NN * 3 * LG];    // node_v @ Wnv
__device__ float g_nvn[NN * LG];        // ||nv||_spatial
__device__ float g_nes[NN * LG];        // segment_sum(es_upd)
__device__ float g_nev[NN * 3 * LG];    // segment_sum(ev_upd)

__device__ __forceinline__ float siluf(float x)  { return x / (1.0f + __expf(-x)); }
__device__ __forceinline__ float sigmf(float x)  { return 1.0f / (1.0f + __expf(-x)); }

// ============================================================================
// Kernel A: node input projections (warp per node) + zero accumulators
// ============================================================================
__global__ void __launch_bounds__(256) k_node_pre(
    const float* __restrict__ node_s, const float* __restrict__ node_v,
    const float* __restrict__ Wns,    const float* __restrict__ bns,
    const float* __restrict__ Wnv)
{
    __shared__ float WnsT[LG][GD];   // transposed: [l][g]
    __shared__ float WnvT[LG][GD];
    for (int i = threadIdx.x; i < GD * LG; i += blockDim.x) {
        int g = i >> 4, l = i & 15;
        WnsT[l][g] = Wns[i];
        WnvT[l][g] = Wnv[i];
    }
    // zero the edge-aggregation accumulators (must finish before k_edge runs;
    // kernel boundary on the same stream guarantees that)
    {
        int idx = blockIdx.x * blockDim.x + threadIdx.x;
        int tot = gridDim.x * blockDim.x;
        for (int i = idx; i < NN * LG; i += tot)     g_nes[i] = 0.0f;
        for (int i = idx; i < NN * 3 * LG; i += tot) g_nev[i] = 0.0f;
    }
    __syncthreads();

    int lane = threadIdx.x & 31;
    int n = blockIdx.x * (blockDim.x >> 5) + (threadIdx.x >> 5);
    if (n >= NN) return;

    // each lane owns 4 consecutive g
    float4 s4 = __ldg((const float4*)(node_s + (size_t)n * GD) + lane);
    float4 v40 = __ldg((const float4*)(node_v + (size_t)n * 3 * GD) + lane);
    float4 v41 = __ldg((const float4*)(node_v + (size_t)n * 3 * GD + GD) + lane);
    float4 v42 = __ldg((const float4*)(node_v + (size_t)n * 3 * GD + 2 * GD) + lane);

    float ps[LG], p0[LG], p1[LG], p2[LG];
#pragma unroll
    for (int l = 0; l < LG; l++) {
        float4 w = *(const float4*)(&WnsT[l][lane * 4]);
        ps[l] = s4.x * w.x + s4.y * w.y + s4.z * w.z + s4.w * w.w;
        float4 u = *(const float4*)(&WnvT[l][lane * 4]);
        p0[l] = v40.x * u.x + v40.y * u.y + v40.z * u.z + v40.w * u.w;
        p1[l] = v41.x * u.x + v41.y * u.y + v41.z * u.z + v41.w * u.w;
        p2[l] = v42.x * u.x + v42.y * u.y + v42.z * u.z + v42.w * u.w;
    }
#pragma unroll
    for (int off = 16; off > 0; off >>= 1) {
#pragma unroll
        for (int l = 0; l < LG; l++) {
            ps[l] += __shfl_xor_sync(0xffffffffu, ps[l], off);
            p0[l] += __shfl_xor_sync(0xffffffffu, p0[l], off);
            p1[l] += __shfl_xor_sync(0xffffffffu, p1[l], off);
            p2[l] += __shfl_xor_sync(0xffffffffu, p2[l], off);
        }
    }
    if (lane < LG) {
        float a = 0.f, b0 = 0.f, b1 = 0.f, b2 = 0.f;
#pragma unroll
        for (int l = 0; l < LG; l++)
            if (lane == l) { a = ps[l]; b0 = p0[l]; b1 = p1[l]; b2 = p2[l]; }
        a += __ldg(bns + lane);
        g_ns[n * LG + lane] = siluf(a);
        g_nv[(size_t)n * 3 * LG + 0 * LG + lane] = b0;
        g_nv[(size_t)n * 3 * LG + 1 * LG + lane] = b1;
        g_nv[(size_t)n * 3 * LG + 2 * LG + lane] = b2;
        g_nvn[n * LG + lane] = sqrtf(b0 * b0 + b1 * b1 + b2 * b2 + 1e-12f);
    }
}

// ============================================================================
// Kernel B: edge update (half-warp per edge, lane = feature l)
// ============================================================================
__global__ void __launch_bounds__(256) k_edge(
    const float* __restrict__ edge_s, const float* __restrict__ edge_v,
    const float* __restrict__ dist,   const float* __restrict__ vctr,
    const int*   __restrict__ src,    const int*   __restrict__ dst,
    const float* __restrict__ Wen,    const float* __restrict__ ben,
    const float* __restrict__ Wtp,    const float* __restrict__ btp,
    const float* __restrict__ Wg1,    const float* __restrict__ bg1,
    const float* __restrict__ Wg2,    const float* __restrict__ bg2,
    const float* __restrict__ Wtv,    const float* __restrict__ btv,
    float* __restrict__ es_out,       float* __restrict__ ev_out)
{
    __shared__ float sWen[32 * 16], sWtp[16 * 16], sWg1[16 * 16], sWg2[16 * 16];
    __shared__ float sWtv[16 * 48];
    __shared__ float sben[16], sbtp[16], sbg1[16], sbg2[16], sbtv[48];
    int t = threadIdx.x;
    for (int i = t; i < 512; i += 256) sWen[i] = Wen[i];
    if (t < 256) { sWtp[t] = Wtp[t]; sWg1[t] = Wg1[t]; sWg2[t] = Wg2[t]; }
    for (int i = t; i < 768; i += 256) sWtv[i] = Wtv[i];
    if (t < 16) { sben[t] = ben[t]; sbtp[t] = btp[t]; sbg1[t] = bg1[t]; sbg2[t] = bg2[t]; }
    if (t < 48) sbtv[t] = btv[t];
    __syncthreads();

    const int l = t & 15;
    const unsigned base = (unsigned)(t & 16);   // half-warp shuffle base (bit 4 of lane)
    int e = blockIdx.x * (blockDim.x >> 4) + (t >> 4);
    bool valid = (e < NE);
    if (!valid) e = 0;

    int s = src[e], d = dst[e];
    float nss = g_ns[s * LG + l];
    float nsd = g_ns[d * LG + l];
    float es  = edge_s[(size_t)e * LG + l];

    // en = [ns[src] | ns[dst]] @ Wen + ben
    float en = sben[l];
#pragma unroll
    for (int k = 0; k < 16; k++) {
        float a = __shfl_sync(0xffffffffu, nss, base + k);
        float b = __shfl_sync(0xffffffffu, nsd, base + k);
        en = fmaf(a, sWen[k * 16 + l], en);
        en = fmaf(b, sWen[(16 + k) * 16 + l], en);
    }
    // tp = edge_s @ Wtp + btp ; tm = en * tp
    float tp = sbtp[l];
#pragma unroll
    for (int k = 0; k < 16; k++)
        tp = fmaf(__shfl_sync(0xffffffffu, es, base + k), sWtp[k * 16 + l], tp);
    float tm = en * tp;
    // gate = sigmoid(silu(tm@Wg1+bg1)@Wg2+bg2)
    float h = sbg1[l];
#pragma unroll
    for (int k = 0; k < 16; k++)
        h = fmaf(__shfl_sync(0xffffffffu, tm, base + k), sWg1[k * 16 + l], h);
    h = siluf(h);
    float gg = sbg2[l];
#pragma unroll
    for (int k = 0; k < 16; k++)
        gg = fmaf(__shfl_sync(0xffffffffu, h, base + k), sWg2[k * 16 + l], gg);
    float gate = sigmf(gg);

    float di = dist[e];
    float co = (di < 10.0f) ? 0.5f * (__cosf(di * 0.31415926535f) + 1.0f) : 0.0f;
    float esu = gate * co;

    // vc = es_upd @ Wtv + btv  -> tc | ec | rc
    float tc = sbtv[l], ec = sbtv[16 + l], rc = sbtv[32 + l];
#pragma unroll
    for (int k = 0; k < 16; k++) {
        float a = __shfl_sync(0xffffffffu, esu, base + k);
        tc = fmaf(a, sWtv[k * 48 + l], tc);
        ec = fmaf(a, sWtv[k * 48 + 16 + l], ec);
        rc = fmaf(a, sWtv[k * 48 + 32 + l], rc);
    }

    if (valid) {
        es_out[(size_t)e * LG + l] = es + esu;
        atomicAdd(&g_nes[d * LG + l], esu);
#pragma unroll
        for (int v = 0; v < 3; v++) {
            float ev  = edge_v[(size_t)e * 3 * LG + v * LG + l];
            float nvv = g_nv[(size_t)s * 3 * LG + v * LG + l];
            float vn  = vctr[(size_t)e * 3 + v];
            float evu = (ev * tc + nvv * ec + vn * rc) * co;
            ev_out[(size_t)e * 3 * LG + v * LG + l] = ev + evu;
            atomicAdd(&g_nev[(size_t)d * 3 * LG + v * LG + l], evu);
        }
    }
}

// ============================================================================
// Kernel C: node output (warp per node): Wonv proj, Wo1/Wo2 MLP,
//           residuals, CoorsNorm, LayerNorm
// ============================================================================
__global__ void __launch_bounds__(256) k_node_post(
    const float* __restrict__ node_s, const float* __restrict__ node_v,
    const float* __restrict__ Wonv,
    const float* __restrict__ Wo1,  const float* __restrict__ bo1,
    const float* __restrict__ Wo2,  const float* __restrict__ bo2,
    const float* __restrict__ ln_g, const float* __restrict__ ln_b,
    const float* __restrict__ cn_scale,
    float* __restrict__ s_out, float* __restrict__ v_out)
{
    __shared__ float sWonv[16 * 128];
    __shared__ float sWo2[16 * 128];
    __shared__ float sWo1[32 * 16];
    __shared__ float sbo1[16];
    int t = threadIdx.x;
    for (int i = t; i < 2048; i += 256) { sWonv[i] = Wonv[i]; sWo2[i] = Wo2[i]; }
    if (t < 512 && t >= 256) {}
    for (int i = t; i < 512; i += 256) sWo1[i] = Wo1[i];
    if (t < 16) sbo1[t] = bo1[t];
    __syncthreads();

    int lane = t & 31;
    int n = blockIdx.x * (blockDim.x >> 5) + (t >> 5);
    if (n >= NN) return;

    float nes = 0.f, nvn = 0.f, q0 = 0.f, q1 = 0.f, q2 = 0.f;
    if (lane < 16) {
        nes = g_nes[n * LG + lane];
        nvn = g_nvn[n * LG + lane];
        q0  = g_nev[(size_t)n * 48 + lane];
        q1  = g_nev[(size_t)n * 48 + 16 + lane];
        q2  = g_nev[(size_t)n * 48 + 32 + lane];
    }

    // h = silu([n_es | nv_norm] @ Wo1 + bo1)  (valid on lanes 0..15, duplicated 16..31)
    int ll = lane & 15;
    float h = sbo1[ll];
#pragma unroll
    for (int k = 0; k < 16; k++) {
        h = fmaf(__shfl_sync(0xffffffffu, nes, k), sWo1[k * 16 + ll], h);
        h = fmaf(__shfl_sync(0xffffffffu, nvn, k), sWo1[(16 + k) * 16 + ll], h);
    }
    h = siluf(h);

    // lane owns g = lane*4 .. lane*4+3
    float4 acc = __ldg((const float4*)bo2 + lane);
    float4 a0 = make_float4(0.f, 0.f, 0.f, 0.f), a1 = a0, a2 = a0;
#pragma unroll
    for (int j = 0; j < 16; j++) {
        float hj = __shfl_sync(0xffffffffu, h, j);
        float4 w2 = *(const float4*)(&sWo2[j * 128 + lane * 4]);
        acc.x = fmaf(hj, w2.x, acc.x); acc.y = fmaf(hj, w2.y, acc.y);
        acc.z = fmaf(hj, w2.z, acc.z); acc.w = fmaf(hj, w2.w, acc.w);
        float b0 = __shfl_sync(0xffffffffu, q0, j);
        float b1 = __shfl_sync(0xffffffffu, q1, j);
        float b2 = __shfl_sync(0xffffffffu, q2, j);
        float4 wv = *(const float4*)(&sWonv[j * 128 + lane * 4]);
        a0.x = fmaf(b0, wv.x, a0.x); a0.y = fmaf(b0, wv.y, a0.y);
        a0.z = fmaf(b0, wv.z, a0.z); a0.w = fmaf(b0, wv.w, a0.w);
        a1.x = fmaf(b1, wv.x, a1.x); a1.y = fmaf(b1, wv.y, a1.y);
        a1.z = fmaf(b1, wv.z, a1.z); a1.w = fmaf(b1, wv.w, a1.w);
        a2.x = fmaf(b2, wv.x, a2.x); a2.y = fmaf(b2, wv.y, a2.y);
        a2.z = fmaf(b2, wv.z, a2.z); a2.w = fmaf(b2, wv.w, a2.w);
    }

    // scalar residual + LayerNorm
    float4 s_in = __ldg((const float4*)(node_s + (size_t)n * GD) + lane);
    float4 so;
    so.x = s_in.x + acc.x; so.y = s_in.y + acc.y;
    so.z = s_in.z + acc.z; so.w = s_in.w + acc.w;
    float sum = so.x + so.y + so.z + so.w;
    float sq  = so.x * so.x + so.y * so.y + so.z * so.z + so.w * so.w;
#pragma unroll
    for (int off = 16; off > 0; off >>= 1) {
        sum += __shfl_xor_sync(0xffffffffu, sum, off);
        sq  += __shfl_xor_sync(0xffffffffu, sq, off);
    }
    float mu  = sum * (1.0f / 128.0f);
    float var = sq * (1.0f / 128.0f) - mu * mu;
    float inv = rsqrtf(var + 1e-5f);
    float4 g4 = __ldg((const float4*)ln_g + lane);
    float4 b4 = __ldg((const float4*)ln_b + lane);
    float4 os;
    os.x = (so.x - mu) * inv * g4.x + b4.x;
    os.y = (so.y - mu) * inv * g4.y + b4.y;
    os.z = (so.z - mu) * inv * g4.z + b4.z;
    os.w = (so.w - mu) * inv * g4.w + b4.w;
    ((float4*)(s_out + (size_t)n * GD))[lane] = os;

    // vector residual + CoorsNorm
    float4 v0 = __ldg((const float4*)(node_v + (size_t)n * 3 * GD) + lane);
    float4 v1 = __ldg((const float4*)(node_v + (size_t)n * 3 * GD + GD) + lane);
    float4 v2 = __ldg((const float4*)(node_v + (size_t)n * 3 * GD + 2 * GD) + lane);
    v0.x += a0.x; v0.y += a0.y; v0.z += a0.z; v0.w += a0.w;
    v1.x += a1.x; v1.y += a1.y; v1.z += a1.z; v1.w += a1.w;
    v2.x += a2.x; v2.y += a2.y; v2.z += a2.z; v2.w += a2.w;
    float4 c4 = __ldg((const float4*)cn_scale + lane);
    float nx = fmaxf(sqrtf(v0.x * v0.x + v1.x * v1.x + v2.x * v2.x), 1e-8f);
    float ny = fmaxf(sqrtf(v0.y * v0.y + v1.y * v1.y + v2.y * v2.y), 1e-8f);
    float nz = fmaxf(sqrtf(v0.z * v0.z + v1.z * v1.z + v2.z * v2.z), 1e-8f);
    float nw = fmaxf(sqrtf(v0.w * v0.w + v1.w * v1.w + v2.w * v2.w), 1e-8f);
    float sx = c4.x / nx, sy = c4.y / ny, sz = c4.z / nz, sw = c4.w / nw;
    v0.x *= sx; v0.y *= sy; v0.z *= sz; v0.w *= sw;
    v1.x *= sx; v1.y *= sy; v1.z *= sz; v1.w *= sw;
    v2.x *= sx; v2.y *= sy; v2.z *= sz; v2.w *= sw;
    ((float4*)(v_out + (size_t)n * 3 * GD))[lane]          = v0;
    ((float4*)(v_out + (size_t)n * 3 * GD + GD))[lane]     = v1;
    ((float4*)(v_out + (size_t)n * 3 * GD + 2 * GD))[lane] = v2;
}

// ============================================================================
extern "C" void kernel_launch(void* const* d_in, const int* in_sizes, int n_in,
                              void* d_out, int out_size)
{
    const float* node_s = (const float*)d_in[0];
    const float* node_v = (const float*)d_in[1];
    const float* edge_s = (const float*)d_in[2];
    const float* edge_v = (const float*)d_in[3];
    const float* dist   = (const float*)d_in[4];
    const float* vctr   = (const float*)d_in[5];
    const int*   src    = (const int*)d_in[6];
    const int*   dst    = (const int*)d_in[7];
    const float* Wns  = (const float*)d_in[8];
    const float* bns  = (const float*)d_in[9];
    const float* Wnv  = (const float*)d_in[10];
    const float* Wen  = (const float*)d_in[11];
    const float* ben  = (const float*)d_in[12];
    const float* Wtp  = (const float*)d_in[13];
    const float* btp  = (const float*)d_in[14];
    const float* Wg1  = (const float*)d_in[15];
    const float* bg1  = (const float*)d_in[16];
    const float* Wg2  = (const float*)d_in[17];
    const float* bg2  = (const float*)d_in[18];
    const float* Wtv  = (const float*)d_in[19];
    const float* btv  = (const float*)d_in[20];
    const float* Wonv = (const float*)d_in[21];
    const float* Wo1  = (const float*)d_in[22];
    const float* bo1  = (const float*)d_in[23];
    const float* Wo2  = (const float*)d_in[24];
    const float* bo2  = (const float*)d_in[25];
    const float* ln_g = (const float*)d_in[26];
    const float* ln_b = (const float*)d_in[27];
    const float* cn_s = (const float*)d_in[28];

    float* out    = (float*)d_out;
    float* s_out  = out;                                 // [N, G]
    float* v_out  = out + (size_t)NN * GD;               // [N, 3, G]
    float* es_out = out + (size_t)NN * GD * 4;           // [E, LG]
    float* ev_out = es_out + (size_t)NE * LG;            // [E, 3, LG]

    int blocksA = (NN * 32 + 255) / 256;   // warp per node
    int blocksB = (NE + 15) / 16;          // half-warp per edge, 256 thr = 16 edges

    k_node_pre<<<blocksA, 256>>>(node_s, node_v, Wns, bns, Wnv);
    k_edge<<<blocksB, 256>>>(edge_s, edge_v, dist, vctr, src, dst,
                             Wen, ben, Wtp, btp, Wg1, bg1, Wg2, bg2, Wtv, btv,
                             es_out, ev_out);
    k_node_post<<<blocksA, 256>>>(node_s, node_v, Wonv, Wo1, bo1, Wo2, bo2,
                                  ln_g, ln_b, cn_s, s_out, v_out);
}

// round 6
// speedup vs baseline: 1.5812x; 1.5812x over previous
#include <cuda_runtime.h>
#include <math.h>

#define NN 50000
#define NE 800000
#define GD 128
#define LG 16

// ---- scratch (device globals: no allocations allowed) ----
__device__ float g_ns [NN * LG];        // silu(node_s @ Wns + bns)
__device__ float g_nv [NN * 3 * LG];    // node_v @ Wnv
__device__ float g_nvn[NN * LG];        // ||nv||_spatial
__device__ float g_nes[NN * LG];        // segment_sum(es_upd)
__device__ float g_nev[NN * 3 * LG];    // segment_sum(ev_upd)

__device__ __forceinline__ float siluf(float x)  { return x / (1.0f + __expf(-x)); }
__device__ __forceinline__ float sigmf(float x)  { return 1.0f / (1.0f + __expf(-x)); }

__device__ __forceinline__ void red_v4(float* p, float a, float b, float c, float d) {
    asm volatile("red.global.add.v4.f32 [%0], {%1, %2, %3, %4};"
                 :: "l"(p), "f"(a), "f"(b), "f"(c), "f"(d) : "memory");
}

// ============================================================================
// Kernel A: node input projections — QUAD per node (thread owns l-quad)
//           + zero accumulators
// ============================================================================
__global__ void __launch_bounds__(256) k_node_pre(
    const float* __restrict__ node_s, const float* __restrict__ node_v,
    const float* __restrict__ Wns,    const float* __restrict__ bns,
    const float* __restrict__ Wnv)
{
    __shared__ float sWns[GD * LG];   // [g][l] row-major, as stored
    __shared__ float sWnv[GD * LG];
    for (int i = threadIdx.x; i < GD * LG; i += blockDim.x) {
        sWns[i] = Wns[i];
        sWnv[i] = Wnv[i];
    }
    // zero the edge-aggregation accumulators (kernel boundary orders vs k_edge)
    {
        int idx = blockIdx.x * blockDim.x + threadIdx.x;
        int tot = gridDim.x * blockDim.x;
        float4 z = make_float4(0.f, 0.f, 0.f, 0.f);
        float4* pes = (float4*)g_nes;   // NN*LG/4   = 200000
        float4* pev = (float4*)g_nev;   // NN*3*LG/4 = 600000
        for (int i = idx; i < NN * LG / 4; i += tot)     pes[i] = z;
        for (int i = idx; i < NN * 3 * LG / 4; i += tot) pev[i] = z;
    }
    __syncthreads();

    const int t    = threadIdx.x;
    const int q    = t & 3;                 // quad index -> l-quad
    const int lq   = q * 4;
    const int lane = t & 31;
    const unsigned qb = (unsigned)(lane & 28);   // quad base lane
    int n = blockIdx.x * 64 + (t >> 2);
    const bool valid = (n < NN);
    if (!valid) n = NN - 1;                 // clamped redundant work, uniform per quad

    const float* srow = node_s + (size_t)n * GD;
    const float* vrow = node_v + (size_t)n * 3 * GD;

    float4 ans = make_float4(0.f, 0.f, 0.f, 0.f);
    float4 av0 = ans, av1 = ans, av2 = ans;

    for (int tile = 0; tile < 4; tile++) {       // 32 g per tile
        float sA[2][4], vA[3][2][4];
#pragma unroll
        for (int j = 0; j < 2; j++) {
            int off = tile * 32 + j * 16 + lq;
            float4 tp = __ldg((const float4*)(srow + off));
            sA[j][0] = tp.x; sA[j][1] = tp.y; sA[j][2] = tp.z; sA[j][3] = tp.w;
#pragma unroll
            for (int v = 0; v < 3; v++) {
                float4 tv = __ldg((const float4*)(vrow + v * GD + off));
                vA[v][j][0] = tv.x; vA[v][j][1] = tv.y; vA[v][j][2] = tv.z; vA[v][j][3] = tv.w;
            }
        }
#pragma unroll
        for (int j = 0; j < 2; j++) {
#pragma unroll
            for (int kq = 0; kq < 4; kq++) {
#pragma unroll
                for (int c = 0; c < 4; c++) {
                    int gl = tile * 32 + j * 16 + kq * 4 + c;
                    float a  = __shfl_sync(0xffffffffu, sA[j][c],    qb + kq);
                    float b0 = __shfl_sync(0xffffffffu, vA[0][j][c], qb + kq);
                    float b1 = __shfl_sync(0xffffffffu, vA[1][j][c], qb + kq);
                    float b2 = __shfl_sync(0xffffffffu, vA[2][j][c], qb + kq);
                    float4 w = *(const float4*)(&sWns[gl * 16 + lq]);
                    float4 u = *(const float4*)(&sWnv[gl * 16 + lq]);
                    ans.x = fmaf(a, w.x, ans.x); ans.y = fmaf(a, w.y, ans.y);
                    ans.z = fmaf(a, w.z, ans.z); ans.w = fmaf(a, w.w, ans.w);
                    av0.x = fmaf(b0, u.x, av0.x); av0.y = fmaf(b0, u.y, av0.y);
                    av0.z = fmaf(b0, u.z, av0.z); av0.w = fmaf(b0, u.w, av0.w);
                    av1.x = fmaf(b1, u.x, av1.x); av1.y = fmaf(b1, u.y, av1.y);
                    av1.z = fmaf(b1, u.z, av1.z); av1.w = fmaf(b1, u.w, av1.w);
                    av2.x = fmaf(b2, u.x, av2.x); av2.y = fmaf(b2, u.y, av2.y);
                    av2.z = fmaf(b2, u.z, av2.z); av2.w = fmaf(b2, u.w, av2.w);
                }
            }
        }
    }

    if (valid) {
        float4 bb = __ldg((const float4*)(bns + lq));
        float4 o;
        o.x = siluf(ans.x + bb.x); o.y = siluf(ans.y + bb.y);
        o.z = siluf(ans.z + bb.z); o.w = siluf(ans.w + bb.w);
        *(float4*)(g_ns + (size_t)n * LG + lq) = o;
        *(float4*)(g_nv + (size_t)n * 48 + lq)      = av0;
        *(float4*)(g_nv + (size_t)n * 48 + 16 + lq) = av1;
        *(float4*)(g_nv + (size_t)n * 48 + 32 + lq) = av2;
        float4 nn;
        nn.x = sqrtf(av0.x * av0.x + av1.x * av1.x + av2.x * av2.x + 1e-12f);
        nn.y = sqrtf(av0.y * av0.y + av1.y * av1.y + av2.y * av2.y + 1e-12f);
        nn.z = sqrtf(av0.z * av0.z + av1.z * av1.z + av2.z * av2.z + 1e-12f);
        nn.w = sqrtf(av0.w * av0.w + av1.w * av1.w + av2.w * av2.w + 1e-12f);
        *(float4*)(g_nvn + (size_t)n * LG + lq) = nn;
    }
}

// ============================================================================
// Kernel B: edge update — QUAD per edge (thread owns l-quad), vector atomics
// ============================================================================
__global__ void __launch_bounds__(256) k_edge(
    const float* __restrict__ edge_s, const float* __restrict__ edge_v,
    const float* __restrict__ dist,   const float* __restrict__ vctr,
    const int*   __restrict__ src,    const int*   __restrict__ dst,
    const float* __restrict__ Wen,    const float* __restrict__ ben,
    const float* __restrict__ Wtp,    const float* __restrict__ btp,
    const float* __restrict__ Wg1,    const float* __restrict__ bg1,
    const float* __restrict__ Wg2,    const float* __restrict__ bg2,
    const float* __restrict__ Wtv,    const float* __restrict__ btv,
    float* __restrict__ es_out,       float* __restrict__ ev_out)
{
    __shared__ float sWen[32 * 16], sWtp[16 * 16], sWg1[16 * 16], sWg2[16 * 16];
    __shared__ float sWtv[16 * 48];
    __shared__ float sben[16], sbtp[16], sbg1[16], sbg2[16], sbtv[48];
    int t = threadIdx.x;
    for (int i = t; i < 512; i += 256) sWen[i] = Wen[i];
    if (t < 256) { sWtp[t] = Wtp[t]; sWg1[t] = Wg1[t]; sWg2[t] = Wg2[t]; }
    for (int i = t; i < 768; i += 256) sWtv[i] = Wtv[i];
    if (t < 16) { sben[t] = ben[t]; sbtp[t] = btp[t]; sbg1[t] = bg1[t]; sbg2[t] = bg2[t]; }
    if (t < 48) sbtv[t] = btv[t];
    __syncthreads();

    const int q  = t & 3;
    const int lq = q * 4;
    const unsigned qb = (unsigned)((t & 31) & 28);
    const int e = blockIdx.x * 64 + (t >> 2);      // NE = 12500 * 64, no guard

    const int s = src[e], d = dst[e];
    float nss[4], nsd[4], es[4];
    {
        float4 a = *(const float4*)(g_ns + (size_t)s * LG + lq);
        nss[0] = a.x; nss[1] = a.y; nss[2] = a.z; nss[3] = a.w;
        float4 b = *(const float4*)(g_ns + (size_t)d * LG + lq);
        nsd[0] = b.x; nsd[1] = b.y; nsd[2] = b.z; nsd[3] = b.w;
        float4 c = __ldg((const float4*)(edge_s + (size_t)e * LG + lq));
        es[0] = c.x; es[1] = c.y; es[2] = c.z; es[3] = c.w;
    }

    // en = [ns[src] | ns[dst]] @ Wen + ben
    float4 en = *(const float4*)(&sben[lq]);
#pragma unroll
    for (int kq = 0; kq < 4; kq++) {
#pragma unroll
        for (int c = 0; c < 4; c++) {
            int k = kq * 4 + c;
            float a = __shfl_sync(0xffffffffu, nss[c], qb + kq);
            float b = __shfl_sync(0xffffffffu, nsd[c], qb + kq);
            float4 w1 = *(const float4*)(&sWen[k * 16 + lq]);
            float4 w2 = *(const float4*)(&sWen[(16 + k) * 16 + lq]);
            en.x = fmaf(a, w1.x, fmaf(b, w2.x, en.x));
            en.y = fmaf(a, w1.y, fmaf(b, w2.y, en.y));
            en.z = fmaf(a, w1.z, fmaf(b, w2.z, en.z));
            en.w = fmaf(a, w1.w, fmaf(b, w2.w, en.w));
        }
    }
    // tp = edge_s @ Wtp + btp ; tm = en * tp
    float4 tp = *(const float4*)(&sbtp[lq]);
#pragma unroll
    for (int kq = 0; kq < 4; kq++) {
#pragma unroll
        for (int c = 0; c < 4; c++) {
            int k = kq * 4 + c;
            float a = __shfl_sync(0xffffffffu, es[c], qb + kq);
            float4 w = *(const float4*)(&sWtp[k * 16 + lq]);
            tp.x = fmaf(a, w.x, tp.x); tp.y = fmaf(a, w.y, tp.y);
            tp.z = fmaf(a, w.z, tp.z); tp.w = fmaf(a, w.w, tp.w);
        }
    }
    float tm[4] = { en.x * tp.x, en.y * tp.y, en.z * tp.z, en.w * tp.w };

    // gate = sigmoid(silu(tm@Wg1+bg1)@Wg2+bg2)
    float4 h4 = *(const float4*)(&sbg1[lq]);
#pragma unroll
    for (int kq = 0; kq < 4; kq++) {
#pragma unroll
        for (int c = 0; c < 4; c++) {
            int k = kq * 4 + c;
            float a = __shfl_sync(0xffffffffu, tm[c], qb + kq);
            float4 w = *(const float4*)(&sWg1[k * 16 + lq]);
            h4.x = fmaf(a, w.x, h4.x); h4.y = fmaf(a, w.y, h4.y);
            h4.z = fmaf(a, w.z, h4.z); h4.w = fmaf(a, w.w, h4.w);
        }
    }
    float hh[4] = { siluf(h4.x), siluf(h4.y), siluf(h4.z), siluf(h4.w) };
    float4 gg = *(const float4*)(&sbg2[lq]);
#pragma unroll
    for (int kq = 0; kq < 4; kq++) {
#pragma unroll
        for (int c = 0; c < 4; c++) {
            int k = kq * 4 + c;
            float a = __shfl_sync(0xffffffffu, hh[c], qb + kq);
            float4 w = *(const float4*)(&sWg2[k * 16 + lq]);
            gg.x = fmaf(a, w.x, gg.x); gg.y = fmaf(a, w.y, gg.y);
            gg.z = fmaf(a, w.z, gg.z); gg.w = fmaf(a, w.w, gg.w);
        }
    }

    const float di = __ldg(dist + e);
    const float co = (di < 10.0f) ? 0.5f * (__cosf(di * 0.31415926535f) + 1.0f) : 0.0f;
    float esu[4] = { sigmf(gg.x) * co, sigmf(gg.y) * co, sigmf(gg.z) * co, sigmf(gg.w) * co };

    // vc = es_upd @ Wtv + btv  -> tc | ec | rc
    float4 tc = *(const float4*)(&sbtv[lq]);
    float4 ec = *(const float4*)(&sbtv[16 + lq]);
    float4 rc = *(const float4*)(&sbtv[32 + lq]);
#pragma unroll
    for (int kq = 0; kq < 4; kq++) {
#pragma unroll
        for (int c = 0; c < 4; c++) {
            int k = kq * 4 + c;
            float a = __shfl_sync(0xffffffffu, esu[c], qb + kq);
            float4 wt = *(const float4*)(&sWtv[k * 48 + lq]);
            float4 we = *(const float4*)(&sWtv[k * 48 + 16 + lq]);
            float4 wr = *(const float4*)(&sWtv[k * 48 + 32 + lq]);
            tc.x = fmaf(a, wt.x, tc.x); tc.y = fmaf(a, wt.y, tc.y);
            tc.z = fmaf(a, wt.z, tc.z); tc.w = fmaf(a, wt.w, tc.w);
            ec.x = fmaf(a, we.x, ec.x); ec.y = fmaf(a, we.y, ec.y);
            ec.z = fmaf(a, we.z, ec.z); ec.w = fmaf(a, we.w, ec.w);
            rc.x = fmaf(a, wr.x, rc.x); rc.y = fmaf(a, wr.y, rc.y);
            rc.z = fmaf(a, wr.z, rc.z); rc.w = fmaf(a, wr.w, rc.w);
        }
    }

    // edge scalar out + scatter
    {
        float4 eso = __ldg((const float4*)(edge_s + (size_t)e * LG + lq));
        eso.x += esu[0]; eso.y += esu[1]; eso.z += esu[2]; eso.w += esu[3];
        *(float4*)(es_out + (size_t)e * LG + lq) = eso;
        red_v4(g_nes + (size_t)d * LG + lq, esu[0], esu[1], esu[2], esu[3]);
    }

    // edge vector out + scatter
#pragma unroll
    for (int v = 0; v < 3; v++) {
        float4 ev  = __ldg((const float4*)(edge_v + (size_t)e * 48 + v * 16 + lq));
        float4 nvv = *(const float4*)(g_nv + (size_t)s * 48 + v * 16 + lq);
        float vn   = __ldg(vctr + (size_t)e * 3 + v);
        float4 evu;
        evu.x = (ev.x * tc.x + nvv.x * ec.x + vn * rc.x) * co;
        evu.y = (ev.y * tc.y + nvv.y * ec.y + vn * rc.y) * co;
        evu.z = (ev.z * tc.z + nvv.z * ec.z + vn * rc.z) * co;
        evu.w = (ev.w * tc.w + nvv.w * ec.w + vn * rc.w) * co;
        float4 evo;
        evo.x = ev.x + evu.x; evo.y = ev.y + evu.y;
        evo.z = ev.z + evu.z; evo.w = ev.w + evu.w;
        *(float4*)(ev_out + (size_t)e * 48 + v * 16 + lq) = evo;
        red_v4(g_nev + (size_t)d * 48 + v * 16 + lq, evu.x, evu.y, evu.z, evu.w);
    }
}

// ============================================================================
// Kernel C: node output (warp per node): Wonv proj, Wo1/Wo2 MLP,
//           residuals, CoorsNorm, LayerNorm  (unchanged — known good)
// ============================================================================
__global__ void __launch_bounds__(256) k_node_post(
    const float* __restrict__ node_s, const float* __restrict__ node_v,
    const float* __restrict__ Wonv,
    const float* __restrict__ Wo1,  const float* __restrict__ bo1,
    const float* __restrict__ Wo2,  const float* __restrict__ bo2,
    const float* __restrict__ ln_g, const float* __restrict__ ln_b,
    const float* __restrict__ cn_scale,
    float* __restrict__ s_out, float* __restrict__ v_out)
{
    __shared__ float sWonv[16 * 128];
    __shared__ float sWo2[16 * 128];
    __shared__ float sWo1[32 * 16];
    __shared__ float sbo1[16];
    int t = threadIdx.x;
    for (int i = t; i < 2048; i += 256) { sWonv[i] = Wonv[i]; sWo2[i] = Wo2[i]; }
    for (int i = t; i < 512; i += 256) sWo1[i] = Wo1[i];
    if (t < 16) sbo1[t] = bo1[t];
    __syncthreads();

    int lane = t & 31;
    int n = blockIdx.x * (blockDim.x >> 5) + (t >> 5);
    if (n >= NN) return;

    float nes = 0.f, nvn = 0.f, q0 = 0.f, q1 = 0.f, q2 = 0.f;
    if (lane < 16) {
        nes = g_nes[n * LG + lane];
        nvn = g_nvn[n * LG + lane];
        q0  = g_nev[(size_t)n * 48 + lane];
        q1  = g_nev[(size_t)n * 48 + 16 + lane];
        q2  = g_nev[(size_t)n * 48 + 32 + lane];
    }

    // h = silu([n_es | nv_norm] @ Wo1 + bo1)
    int ll = lane & 15;
    float h = sbo1[ll];
#pragma unroll
    for (int k = 0; k < 16; k++) {
        h = fmaf(__shfl_sync(0xffffffffu, nes, k), sWo1[k * 16 + ll], h);
        h = fmaf(__shfl_sync(0xffffffffu, nvn, k), sWo1[(16 + k) * 16 + ll], h);
    }
    h = siluf(h);

    // lane owns g = lane*4 .. lane*4+3
    float4 acc = __ldg((const float4*)bo2 + lane);
    float4 a0 = make_float4(0.f, 0.f, 0.f, 0.f), a1 = a0, a2 = a0;
#pragma unroll
    for (int j = 0; j < 16; j++) {
        float hj = __shfl_sync(0xffffffffu, h, j);
        float4 w2 = *(const float4*)(&sWo2[j * 128 + lane * 4]);
        acc.x = fmaf(hj, w2.x, acc.x); acc.y = fmaf(hj, w2.y, acc.y);
        acc.z = fmaf(hj, w2.z, acc.z); acc.w = fmaf(hj, w2.w, acc.w);
        float b0 = __shfl_sync(0xffffffffu, q0, j);
        float b1 = __shfl_sync(0xffffffffu, q1, j);
        float b2 = __shfl_sync(0xffffffffu, q2, j);
        float4 wv = *(const float4*)(&sWonv[j * 128 + lane * 4]);
        a0.x = fmaf(b0, wv.x, a0.x); a0.y = fmaf(b0, wv.y, a0.y);
        a0.z = fmaf(b0, wv.z, a0.z); a0.w = fmaf(b0, wv.w, a0.w);
        a1.x = fmaf(b1, wv.x, a1.x); a1.y = fmaf(b1, wv.y, a1.y);
        a1.z = fmaf(b1, wv.z, a1.z); a1.w = fmaf(b1, wv.w, a1.w);
        a2.x = fmaf(b2, wv.x, a2.x); a2.y = fmaf(b2, wv.y, a2.y);
        a2.z = fmaf(b2, wv.z, a2.z); a2.w = fmaf(b2, wv.w, a2.w);
    }

    // scalar residual + LayerNorm
    float4 s_in = __ldg((const float4*)(node_s + (size_t)n * GD) + lane);
    float4 so;
    so.x = s_in.x + acc.x; so.y = s_in.y + acc.y;
    so.z = s_in.z + acc.z; so.w = s_in.w + acc.w;
    float sum = so.x + so.y + so.z + so.w;
    float sq  = so.x * so.x + so.y * so.y + so.z * so.z + so.w * so.w;
#pragma unroll
    for (int off = 16; off > 0; off >>= 1) {
        sum += __shfl_xor_sync(0xffffffffu, sum, off);
        sq  += __shfl_xor_sync(0xffffffffu, sq, off);
    }
    float mu  = sum * (1.0f / 128.0f);
    float var = sq * (1.0f / 128.0f) - mu * mu;
    float inv = rsqrtf(var + 1e-5f);
    float4 g4 = __ldg((const float4*)ln_g + lane);
    float4 b4 = __ldg((const float4*)ln_b + lane);
    float4 os;
    os.x = (so.x - mu) * inv * g4.x + b4.x;
    os.y = (so.y - mu) * inv * g4.y + b4.y;
    os.z = (so.z - mu) * inv * g4.z + b4.z;
    os.w = (so.w - mu) * inv * g4.w + b4.w;
    ((float4*)(s_out + (size_t)n * GD))[lane] = os;

    // vector residual + CoorsNorm
    float4 v0 = __ldg((const float4*)(node_v + (size_t)n * 3 * GD) + lane);
    float4 v1 = __ldg((const float4*)(node_v + (size_t)n * 3 * GD + GD) + lane);
    float4 v2 = __ldg((const float4*)(node_v + (size_t)n * 3 * GD + 2 * GD) + lane);
    v0.x += a0.x; v0.y += a0.y; v0.z += a0.z; v0.w += a0.w;
    v1.x += a1.x; v1.y += a1.y; v1.z += a1.z; v1.w += a1.w;
    v2.x += a2.x; v2.y += a2.y; v2.z += a2.z; v2.w += a2.w;
    float4 c4 = __ldg((const float4*)cn_scale + lane);
    float nx = fmaxf(sqrtf(v0.x * v0.x + v1.x * v1.x + v2.x * v2.x), 1e-8f);
    float ny = fmaxf(sqrtf(v0.y * v0.y + v1.y * v1.y + v2.y * v2.y), 1e-8f);
    float nz = fmaxf(sqrtf(v0.z * v0.z + v1.z * v1.z + v2.z * v2.z), 1e-8f);
    float nw = fmaxf(sqrtf(v0.w * v0.w + v1.w * v1.w + v2.w * v2.w), 1e-8f);
    float sx = c4.x / nx, sy = c4.y / ny, sz = c4.z / nz, sw = c4.w / nw;
    v0.x *= sx; v0.y *= sy; v0.z *= sz; v0.w *= sw;
    v1.x *= sx; v1.y *= sy; v1.z *= sz; v1.w *= sw;
    v2.x *= sx; v2.y *= sy; v2.z *= sz; v2.w *= sw;
    ((float4*)(v_out + (size_t)n * 3 * GD))[lane]          = v0;
    ((float4*)(v_out + (size_t)n * 3 * GD + GD))[lane]     = v1;
    ((float4*)(v_out + (size_t)n * 3 * GD + 2 * GD))[lane] = v2;
}

// ============================================================================
extern "C" void kernel_launch(void* const* d_in, const int* in_sizes, int n_in,
                              void* d_out, int out_size)
{
    const float* node_s = (const float*)d_in[0];
    const float* node_v = (const float*)d_in[1];
    const float* edge_s = (const float*)d_in[2];
    const float* edge_v = (const float*)d_in[3];
    const float* dist   = (const float*)d_in[4];
    const float* vctr   = (const float*)d_in[5];
    const int*   src    = (const int*)d_in[6];
    const int*   dst    = (const int*)d_in[7];
    const float* Wns  = (const float*)d_in[8];
    const float* bns  = (const float*)d_in[9];
    const float* Wnv  = (const float*)d_in[10];
    const float* Wen  = (const float*)d_in[11];
    const float* ben  = (const float*)d_in[12];
    const float* Wtp  = (const float*)d_in[13];
    const float* btp  = (const float*)d_in[14];
    const float* Wg1  = (const float*)d_in[15];
    const float* bg1  = (const float*)d_in[16];
    const float* Wg2  = (const float*)d_in[17];
    const float* bg2  = (const float*)d_in[18];
    const float* Wtv  = (const float*)d_in[19];
    const float* btv  = (const float*)d_in[20];
    const float* Wonv = (const float*)d_in[21];
    const float* Wo1  = (const float*)d_in[22];
    const float* bo1  = (const float*)d_in[23];
    const float* Wo2  = (const float*)d_in[24];
    const float* bo2  = (const float*)d_in[25];
    const float* ln_g = (const float*)d_in[26];
    const float* ln_b = (const float*)d_in[27];
    const float* cn_s = (const float*)d_in[28];

    float* out    = (float*)d_out;
    float* s_out  = out;                                 // [N, G]
    float* v_out  = out + (size_t)NN * GD;               // [N, 3, G]
    float* es_out = out + (size_t)NN * GD * 4;           // [E, LG]
    float* ev_out = es_out + (size_t)NE * LG;            // [E, 3, LG]

    int blocksPre  = (NN + 63) / 64;       // quad per node, 64 nodes/block
    int blocksEdge = NE / 64;              // quad per edge, 64 edges/block (exact)
    int blocksPost = (NN * 32 + 255) / 256;

    k_node_pre<<<blocksPre, 256>>>(node_s, node_v, Wns, bns, Wnv);
    k_edge<<<blocksEdge, 256>>>(edge_s, edge_v, dist, vctr, src, dst,
                                Wen, ben, Wtp, btp, Wg1, bg1, Wg2, bg2, Wtv, btv,
                                es_out, ev_out);
    k_node_post<<<blocksPost, 256>>>(node_s, node_v, Wonv, Wo1, bo1, Wo2, bo2,
                                     ln_g, ln_b, cn_s, s_out, v_out);
}